// round 4
// baseline (speedup 1.0000x reference)
#include <cuda_runtime.h>
#include <cuda_bf16.h>
#include <math.h>
#include <stdint.h>

// Problem constants
#define Bb 4
#define Ss 2048
#define Dd 768
#define Hh 12
#define Ff 3072
#define Ll 4
#define DHh 64
#define Mrows (Bb*Ss)   // 8192

// ---------------------------------------------------------------------------
// Scratch (device globals; allocation is forbidden)
// ---------------------------------------------------------------------------
__device__ float g_x[Bb*Ss*Dd];     // running activations (h)
__device__ float g_q[Bb*Ss*Dd];     // q / attn_out scratch
__device__ float g_k[Bb*Ss*Dd];
__device__ float g_v[Bb*Ss*Dd];
__device__ float g_attn[Bb*Ss*Dd];  // av merged / ffn out
__device__ float g_mid[Bb*Ss*Ff];   // ffn intermediate

// Pre-split activations (bf16 hi/lo), sized for the largest GEMM input
__device__ __nv_bfloat16 g_ah[Bb*Ss*Ff];
__device__ __nv_bfloat16 g_al[Bb*Ss*Ff];

// Preprocessed (transposed [N,K] K-major, bf16 hi/lo split) weights
__device__ __nv_bfloat16 g_wqkv_h[Ll*3*Dd*Dd];
__device__ __nv_bfloat16 g_wqkv_l[Ll*3*Dd*Dd];
__device__ __nv_bfloat16 g_wo_h[Ll*Dd*Dd];
__device__ __nv_bfloat16 g_wo_l[Ll*Dd*Dd];
__device__ __nv_bfloat16 g_w1_h[Ll*Ff*Dd];
__device__ __nv_bfloat16 g_w1_l[Ll*Ff*Dd];
__device__ __nv_bfloat16 g_w2_h[Ll*Dd*Ff];
__device__ __nv_bfloat16 g_w2_l[Ll*Dd*Ff];

__device__ __forceinline__ float gelu_exact(float v) {
    return 0.5f * v * (1.0f + erff(v * 0.70710678118654752f));
}

__device__ __forceinline__ void mma16816(float* c, const uint32_t* a,
                                         const uint32_t* b) {
    asm volatile(
        "mma.sync.aligned.m16n8k16.row.col.f32.bf16.bf16.f32 "
        "{%0,%1,%2,%3}, {%4,%5,%6,%7}, {%8,%9}, {%0,%1,%2,%3};"
        : "+f"(c[0]), "+f"(c[1]), "+f"(c[2]), "+f"(c[3])
        : "r"(a[0]), "r"(a[1]), "r"(a[2]), "r"(a[3]), "r"(b[0]), "r"(b[1]));
}

__device__ __forceinline__ void ldmx4(uint32_t* r, uint32_t addr) {
    asm volatile(
        "ldmatrix.sync.aligned.m8n8.x4.shared.b16 {%0,%1,%2,%3}, [%4];"
        : "=r"(r[0]), "=r"(r[1]), "=r"(r[2]), "=r"(r[3]) : "r"(addr));
}

__device__ __forceinline__ uint32_t smem_u32(const void* p) {
    uint32_t a;
    asm("{ .reg .u64 tmp; cvta.to.shared.u64 tmp, %1; cvt.u32.u64 %0, tmp; }"
        : "=r"(a) : "l"(p));
    return a;
}

#define CP_ASYNC16(dst, src) \
    asm volatile("cp.async.cg.shared.global [%0], [%1], 16;" \
                 :: "r"(dst), "l"(src))
#define CP_COMMIT() asm volatile("cp.async.commit_group;")
#define CP_WAIT1()  asm volatile("cp.async.wait_group 1;")
#define CP_WAIT0()  asm volatile("cp.async.wait_group 0;")

// ---------------------------------------------------------------------------
// Weight preprocessing: out[n][k] = W[k][n] as bf16 hi + bf16 lo.
// ---------------------------------------------------------------------------
__global__ void __launch_bounds__(256) transpose_split_kernel(
    const float* __restrict__ W, __nv_bfloat16* __restrict__ oh,
    __nv_bfloat16* __restrict__ ol, int K, int N, int rowOff,
    size_t inLS, size_t outLS)
{
    __shared__ float tile[32][33];
    const float* Wl = W + (size_t)blockIdx.z * inLS;
    __nv_bfloat16* ohl = oh + (size_t)blockIdx.z * outLS;
    __nv_bfloat16* oll = ol + (size_t)blockIdx.z * outLS;
    const int nb = blockIdx.x * 32, kb = blockIdx.y * 32;
    const int tx = threadIdx.x, ty = threadIdx.y;
    #pragma unroll
    for (int j = 0; j < 32; j += 8)
        tile[ty + j][tx] = Wl[(size_t)(kb + ty + j) * N + nb + tx];
    __syncthreads();
    #pragma unroll
    for (int j = 0; j < 32; j += 8) {
        float v = tile[tx][ty + j];
        int n = nb + ty + j, k = kb + tx;
        __nv_bfloat16 h  = __float2bfloat16(v);
        __nv_bfloat16 lo = __float2bfloat16(v - __bfloat162float(h));
        ohl[(size_t)(rowOff + n) * K + k] = h;
        oll[(size_t)(rowOff + n) * K + k] = lo;
    }
}

// ---------------------------------------------------------------------------
// Activation split: fp32 -> bf16 hi + bf16 lo, elementwise. n % 2048 == 0.
// ---------------------------------------------------------------------------
__global__ void __launch_bounds__(256) split_act_kernel(
    const float* __restrict__ in, __nv_bfloat16* __restrict__ oh,
    __nv_bfloat16* __restrict__ ol, int n)
{
    int base = (blockIdx.x * 256 + threadIdx.x) * 8;
    if (base >= n) return;
    float4 v0 = *(const float4*)(in + base);
    float4 v1 = *(const float4*)(in + base + 4);
    __nv_bfloat16 h[8], l[8];
    const float* v = (const float*)&v0;
    #pragma unroll
    for (int i = 0; i < 8; i++) {
        float x = (i < 4) ? v[i] : ((const float*)&v1)[i - 4];
        h[i] = __float2bfloat16(x);
        l[i] = __float2bfloat16(x - __bfloat162float(h[i]));
    }
    *(uint4*)(oh + base) = *(uint4*)h;
    *(uint4*)(ol + base) = *(uint4*)l;
}

// ---------------------------------------------------------------------------
// Tensor-core GEMM (mma.sync + ldmatrix + cp.async, base-target safe).
// C[M,N] = A[M,K] @ Wt[N,K]^T, 3-term bf16 split (AhWh + AhWl + AlWh).
// CTA tile 128x128, BK=32, 3-stage cp.async pipeline, 8 warps (32x64 each).
// mode: 0 = +bias, 1 = +bias +exact GELU, 2 = QKV split (768-col outputs).
// ---------------------------------------------------------------------------
#define BKP 40                        // padded K ld (elements) -> 80B rows
#define TILE_E (128 * BKP)            // 5120 elems per tile buffer
#define STAGE_E (4 * TILE_E)          // Ah, Al, Wh, Wl
#define NSTAGE 3
#define GEMM_SMEM (NSTAGE * STAGE_E * 2)   // 122880 bytes

__global__ void __launch_bounds__(256, 1)
tc_gemm_kernel(const __nv_bfloat16* __restrict__ Ah,
               const __nv_bfloat16* __restrict__ Al,
               const __nv_bfloat16* __restrict__ Wh,
               const __nv_bfloat16* __restrict__ Wl,
               const float* __restrict__ bias,
               float* __restrict__ C0, float* __restrict__ C1,
               float* __restrict__ C2,
               int N, int K, int mode)
{
    extern __shared__ __nv_bfloat16 sm[];
    const uint32_t sb = smem_u32(sm);
    const int t   = threadIdx.x;
    const int wid = t >> 5, l = t & 31;
    const int wm  = wid & 3;          // m block (32 rows)
    const int wn  = wid >> 2;         // n block (64 cols)
    const int n0  = blockIdx.x * 128;
    const int m0  = blockIdx.y * 128;

    // Tile-base gmem pointers (row stride K)
    const __nv_bfloat16* gsrc[4];
    gsrc[0] = Ah + (size_t)m0 * K;
    gsrc[1] = Al + (size_t)m0 * K;
    gsrc[2] = Wh + (size_t)n0 * K;
    gsrc[3] = Wl + (size_t)n0 * K;

    // cp.async indices: chunk idx -> row = idx>>2, 16B chunk c = idx&3
    const int r0c = t >> 2, c0c = t & 3;          // idx = t
    const int r1c = (t + 256) >> 2;               // idx = t + 256 (same c)

    float acc[2][8][4];
    #pragma unroll
    for (int m = 0; m < 2; m++)
        #pragma unroll
        for (int n = 0; n < 8; n++)
            #pragma unroll
            for (int e = 0; e < 4; e++) acc[m][n][e] = 0.f;

    const int nIter = K >> 5;

    // Stage loader
    auto load_stage = [&](int it, int buf) {
        const int k0 = it << 5;
        const uint32_t sbase = sb + buf * (STAGE_E * 2);
        #pragma unroll
        for (int tile = 0; tile < 4; tile++) {
            const __nv_bfloat16* g = gsrc[tile];
            uint32_t tb = sbase + tile * (TILE_E * 2);
            CP_ASYNC16(tb + (r0c * BKP + c0c * 8) * 2,
                       g + (size_t)r0c * K + k0 + c0c * 8);
            CP_ASYNC16(tb + (r1c * BKP + c0c * 8) * 2,
                       g + (size_t)r1c * K + k0 + c0c * 8);
        }
    };

    load_stage(0, 0); CP_COMMIT();
    load_stage(1, 1); CP_COMMIT();

    // ldmatrix lane addressing
    const int lrow = l & 15;           // row within 16-row group
    const int lseg = (l >> 4) * 8;     // k-half segment (elements)

    int cb = 0;   // compute buffer
    for (int it = 0; it < nIter; it++) {
        CP_WAIT1();
        __syncthreads();

        if (it + 2 < nIter) {
            int lb = cb + 2; if (lb >= NSTAGE) lb -= NSTAGE;
            load_stage(it + 2, lb);
            CP_COMMIT();
        }

        const uint32_t sAh = sb + cb * (STAGE_E * 2);
        const uint32_t sAl = sAh + TILE_E * 2;
        const uint32_t sWh = sAh + 2 * (TILE_E * 2);
        const uint32_t sWl = sAh + 3 * (TILE_E * 2);

        #pragma unroll
        for (int ks = 0; ks < 2; ks++) {
            const int kofs = (ks * 16 + lseg) * 2;   // bytes
            uint32_t ah[2][4], al[2][4];
            #pragma unroll
            for (int mb = 0; mb < 2; mb++) {
                uint32_t ro = (wm * 32 + mb * 16 + lrow) * (BKP * 2);
                ldmx4(ah[mb], sAh + ro + kofs);
                ldmx4(al[mb], sAl + ro + kofs);
            }
            uint32_t bh[8][2], bl[8][2];
            #pragma unroll
            for (int g = 0; g < 4; g++) {
                uint32_t ro = (wn * 64 + g * 16 + lrow) * (BKP * 2);
                uint32_t r4[4];
                ldmx4(r4, sWh + ro + kofs);
                bh[2*g][0] = r4[0]; bh[2*g][1] = r4[2];
                bh[2*g+1][0] = r4[1]; bh[2*g+1][1] = r4[3];
                ldmx4(r4, sWl + ro + kofs);
                bl[2*g][0] = r4[0]; bl[2*g][1] = r4[2];
                bl[2*g+1][0] = r4[1]; bl[2*g+1][1] = r4[3];
            }
            #pragma unroll
            for (int n = 0; n < 8; n++) {
                #pragma unroll
                for (int m = 0; m < 2; m++) {
                    mma16816(acc[m][n], ah[m], bh[n]);
                    mma16816(acc[m][n], al[m], bh[n]);
                    mma16816(acc[m][n], ah[m], bl[n]);
                }
            }
        }
        __syncthreads();
        cb++; if (cb >= NSTAGE) cb = 0;
    }

    // Epilogue
    float* dst; int nbase; size_t Nout;
    if (mode == 2) {
        int which = n0 / 768;
        dst = (which == 0) ? C0 : ((which == 1) ? C1 : C2);
        nbase = n0 % 768;
        Nout = 768;
    } else {
        dst = C0; nbase = n0; Nout = (size_t)N;
    }
    const int rbase = m0 + wm * 32 + (l >> 2);
    #pragma unroll
    for (int m = 0; m < 2; m++) {
        #pragma unroll
        for (int n = 0; n < 8; n++) {
            int colA = n0 + wn * 64 + n * 8 + (l & 3) * 2;    // bias index
            int colC = nbase + wn * 64 + n * 8 + (l & 3) * 2; // store index
            float b0 = bias ? bias[colA]     : 0.f;
            float b1 = bias ? bias[colA + 1] : 0.f;
            float v0 = acc[m][n][0] + b0;
            float v1 = acc[m][n][1] + b1;
            float v2 = acc[m][n][2] + b0;
            float v3 = acc[m][n][3] + b1;
            if (mode == 1) {
                v0 = gelu_exact(v0); v1 = gelu_exact(v1);
                v2 = gelu_exact(v2); v3 = gelu_exact(v3);
            }
            size_t r0 = (size_t)(rbase + m * 16) * Nout + colC;
            size_t r1 = (size_t)(rbase + m * 16 + 8) * Nout + colC;
            *(float2*)&dst[r0] = make_float2(v0, v1);
            *(float2*)&dst[r1] = make_float2(v2, v3);
        }
    }
}

// ----------------------------------------------------------------------------
// Flash attention (causal), fp32, one 64-row Q tile per block, 256 threads.
// ----------------------------------------------------------------------------
#define FLASH_LD 68
#define FLASH_SMEM (3 * 64 * FLASH_LD * 4)

__global__ void __launch_bounds__(256) flash_attn_kernel(
    const float* __restrict__ Q, const float* __restrict__ Kt,
    const float* __restrict__ Vt, float* __restrict__ O)
{
    extern __shared__ float smf[];
    float* Qs = smf;
    float* Ks = smf + 64 * FLASH_LD;
    float* Vs = smf + 2 * 64 * FLASH_LD;

    const int qt = blockIdx.x;
    const int bh = blockIdx.y;
    const int b  = bh / Hh;
    const int h  = bh % Hh;
    const int t  = threadIdx.x;
    const int r  = t >> 2;
    const int kq = t & 3;
    const int cg = (t & 3) * 16;

    const size_t base = (size_t)b * Ss * Dd + (size_t)h * DHh;

    for (int idx = t; idx < 64 * 16; idx += 256) {
        int i  = idx >> 4;
        int dq = (idx & 15) * 4;
        *(float4*)&Qs[i * FLASH_LD + dq] =
            *(const float4*)(Q + base + (size_t)(qt * 64 + i) * Dd + dq);
    }

    float m = -1e30f, l = 0.f;
    float acc[16];
    #pragma unroll
    for (int i = 0; i < 16; i++) acc[i] = 0.f;

    for (int jt = 0; jt <= qt; jt++) {
        __syncthreads();
        for (int idx = t; idx < 64 * 16; idx += 256) {
            int i  = idx >> 4;
            int dq = (idx & 15) * 4;
            *(float4*)&Ks[i * FLASH_LD + dq] =
                *(const float4*)(Kt + base + (size_t)(jt * 64 + i) * Dd + dq);
            *(float4*)&Vs[i * FLASH_LD + dq] =
                *(const float4*)(Vt + base + (size_t)(jt * 64 + i) * Dd + dq);
        }
        __syncthreads();

        float s[16];
        #pragma unroll
        for (int kk = 0; kk < 16; kk++) s[kk] = 0.f;
        #pragma unroll 4
        for (int d4 = 0; d4 < 64; d4 += 4) {
            float4 q4 = *(const float4*)&Qs[r * FLASH_LD + d4];
            #pragma unroll
            for (int kk = 0; kk < 16; kk++) {
                float4 k4 = *(const float4*)&Ks[(kq + 4 * kk) * FLASH_LD + d4];
                s[kk] = fmaf(q4.x, k4.x,
                        fmaf(q4.y, k4.y,
                        fmaf(q4.z, k4.z,
                        fmaf(q4.w, k4.w, s[kk]))));
            }
        }

        float mloc = -1e30f;
        const bool diag = (jt == qt);
        #pragma unroll
        for (int kk = 0; kk < 16; kk++) {
            float sv = s[kk] * 0.125f;
            if (diag && (kq + 4 * kk) > r) sv = -1e9f;
            s[kk] = sv;
            mloc = fmaxf(mloc, sv);
        }
        mloc = fmaxf(mloc, __shfl_xor_sync(0xffffffffu, mloc, 1));
        mloc = fmaxf(mloc, __shfl_xor_sync(0xffffffffu, mloc, 2));

        const float mnew  = fmaxf(m, mloc);
        const float scale = __expf(m - mnew);

        float lloc = 0.f;
        #pragma unroll
        for (int kk = 0; kk < 16; kk++) {
            s[kk] = __expf(s[kk] - mnew);
            lloc += s[kk];
        }
        lloc += __shfl_xor_sync(0xffffffffu, lloc, 1);
        lloc += __shfl_xor_sync(0xffffffffu, lloc, 2);
        l = l * scale + lloc;
        m = mnew;
        #pragma unroll
        for (int i = 0; i < 16; i++) acc[i] *= scale;

        __syncthreads();
        #pragma unroll
        for (int kk = 0; kk < 16; kk++)
            Ks[r * FLASH_LD + kq + 4 * kk] = s[kk];
        __syncthreads();

        #pragma unroll 8
        for (int j = 0; j < 64; j++) {
            float pj = Ks[r * FLASH_LD + j];
            const float* vrow = &Vs[j * FLASH_LD + cg];
            float4 v0 = *(const float4*)&vrow[0];
            float4 v1 = *(const float4*)&vrow[4];
            float4 v2 = *(const float4*)&vrow[8];
            float4 v3 = *(const float4*)&vrow[12];
            acc[0]  = fmaf(pj, v0.x, acc[0]);
            acc[1]  = fmaf(pj, v0.y, acc[1]);
            acc[2]  = fmaf(pj, v0.z, acc[2]);
            acc[3]  = fmaf(pj, v0.w, acc[3]);
            acc[4]  = fmaf(pj, v1.x, acc[4]);
            acc[5]  = fmaf(pj, v1.y, acc[5]);
            acc[6]  = fmaf(pj, v1.z, acc[6]);
            acc[7]  = fmaf(pj, v1.w, acc[7]);
            acc[8]  = fmaf(pj, v2.x, acc[8]);
            acc[9]  = fmaf(pj, v2.y, acc[9]);
            acc[10] = fmaf(pj, v2.z, acc[10]);
            acc[11] = fmaf(pj, v2.w, acc[11]);
            acc[12] = fmaf(pj, v3.x, acc[12]);
            acc[13] = fmaf(pj, v3.y, acc[13]);
            acc[14] = fmaf(pj, v3.z, acc[14]);
            acc[15] = fmaf(pj, v3.w, acc[15]);
        }
    }

    const float inv = 1.f / l;
    float* orow = O + base + (size_t)(qt * 64 + r) * Dd + cg;
    #pragma unroll
    for (int c = 0; c < 4; c++) {
        float4 o;
        o.x = acc[c * 4 + 0] * inv;
        o.y = acc[c * 4 + 1] * inv;
        o.z = acc[c * 4 + 2] * inv;
        o.w = acc[c * 4 + 3] * inv;
        *(float4*)&orow[c * 4] = o;
    }
}

// ----------------------------------------------------------------------------
// Fused residual + LayerNorm
// ----------------------------------------------------------------------------
__global__ void __launch_bounds__(256) ln_kernel(
    const float* __restrict__ A, const float* __restrict__ Badd,
    const float* __restrict__ gw, const float* __restrict__ bw,
    float* __restrict__ out)
{
    __shared__ float red[64];
    __shared__ float smu, sinv;
    const size_t row = blockIdx.x;
    const int t = threadIdx.x;
    const size_t off = row * Dd;

    float v0 = A[off + t]       + Badd[off + t];
    float v1 = A[off + 256 + t] + Badd[off + 256 + t];
    float v2 = A[off + 512 + t] + Badd[off + 512 + t];

    float s  = v0 + v1 + v2;
    float s2 = v0 * v0 + v1 * v1 + v2 * v2;
    #pragma unroll
    for (int o = 16; o; o >>= 1) {
        s  += __shfl_xor_sync(0xffffffffu, s, o);
        s2 += __shfl_xor_sync(0xffffffffu, s2, o);
    }
    const int w = t >> 5;
    if ((t & 31) == 0) { red[w] = s; red[w + 32] = s2; }
    __syncthreads();
    if (t == 0) {
        float S = 0.f, S2 = 0.f;
        #pragma unroll
        for (int i = 0; i < 8; i++) { S += red[i]; S2 += red[i + 32]; }
        float mu  = S * (1.f / 768.f);
        float var = S2 * (1.f / 768.f) - mu * mu;
        smu  = mu;
        sinv = rsqrtf(var + 1e-5f);
    }
    __syncthreads();
    const float mu = smu, inv = sinv;
    out[off + t]       = (v0 - mu) * inv * gw[t]       + bw[t];
    out[off + 256 + t] = (v1 - mu) * inv * gw[t + 256] + bw[t + 256];
    out[off + 512 + t] = (v2 - mu) * inv * gw[t + 512] + bw[t + 512];
}

// ----------------------------------------------------------------------------
// Host launcher
// ----------------------------------------------------------------------------
extern "C" void kernel_launch(void* const* d_in, const int* in_sizes, int n_in,
                              void* d_out, int out_size)
{
    (void)in_sizes; (void)n_in; (void)out_size;

    const float* x     = (const float*)d_in[0];
    const float* Wq    = (const float*)d_in[2];
    const float* Wk    = (const float*)d_in[3];
    const float* Wv    = (const float*)d_in[4];
    const float* Wo    = (const float*)d_in[5];
    const float* bo    = (const float*)d_in[6];
    const float* ln1_g = (const float*)d_in[7];
    const float* ln1_b = (const float*)d_in[8];
    const float* W1    = (const float*)d_in[9];
    const float* b1    = (const float*)d_in[10];
    const float* W2    = (const float*)d_in[11];
    const float* b2    = (const float*)d_in[12];
    const float* ln2_g = (const float*)d_in[13];
    const float* ln2_b = (const float*)d_in[14];

    float *px, *pq, *pk, *pv, *pattn, *pmid;
    cudaGetSymbolAddress((void**)&px,    g_x);
    cudaGetSymbolAddress((void**)&pq,    g_q);
    cudaGetSymbolAddress((void**)&pk,    g_k);
    cudaGetSymbolAddress((void**)&pv,    g_v);
    cudaGetSymbolAddress((void**)&pattn, g_attn);
    cudaGetSymbolAddress((void**)&pmid,  g_mid);

    __nv_bfloat16 *pah, *pal;
    cudaGetSymbolAddress((void**)&pah, g_ah);
    cudaGetSymbolAddress((void**)&pal, g_al);

    __nv_bfloat16 *qkvh, *qkvl, *woh, *wol, *w1h, *w1l, *w2h, *w2l;
    cudaGetSymbolAddress((void**)&qkvh, g_wqkv_h);
    cudaGetSymbolAddress((void**)&qkvl, g_wqkv_l);
    cudaGetSymbolAddress((void**)&woh,  g_wo_h);
    cudaGetSymbolAddress((void**)&wol,  g_wo_l);
    cudaGetSymbolAddress((void**)&w1h,  g_w1_h);
    cudaGetSymbolAddress((void**)&w1l,  g_w1_l);
    cudaGetSymbolAddress((void**)&w2h,  g_w2_h);
    cudaGetSymbolAddress((void**)&w2l,  g_w2_l);

    cudaFuncSetAttribute(flash_attn_kernel,
                         cudaFuncAttributeMaxDynamicSharedMemorySize, FLASH_SMEM);
    cudaFuncSetAttribute(tc_gemm_kernel,
                         cudaFuncAttributeMaxDynamicSharedMemorySize, GEMM_SMEM);

    const size_t DD = (size_t)Dd * Dd;
    const size_t DF = (size_t)Dd * Ff;
    const int nD = Mrows * Dd;          // 6.29M
    const int nF = Mrows * Ff;          // 25.2M

    // Preprocess weights: transpose to [N,K] + bf16 hi/lo split, all layers.
    {
        dim3 tb(32, 8);
        transpose_split_kernel<<<dim3(Dd/32, Dd/32, Ll), tb>>>(
            Wq, qkvh, qkvl, Dd, Dd, 0,    DD, 3 * DD);
        transpose_split_kernel<<<dim3(Dd/32, Dd/32, Ll), tb>>>(
            Wk, qkvh, qkvl, Dd, Dd, 768,  DD, 3 * DD);
        transpose_split_kernel<<<dim3(Dd/32, Dd/32, Ll), tb>>>(
            Wv, qkvh, qkvl, Dd, Dd, 1536, DD, 3 * DD);
        transpose_split_kernel<<<dim3(Dd/32, Dd/32, Ll), tb>>>(
            Wo, woh, wol, Dd, Dd, 0, DD, DD);
        transpose_split_kernel<<<dim3(Ff/32, Dd/32, Ll), tb>>>(
            W1, w1h, w1l, Dd, Ff, 0, DF, DF);
        transpose_split_kernel<<<dim3(Dd/32, Ff/32, Ll), tb>>>(
            W2, w2h, w2l, Ff, Dd, 0, DF, DF);
    }

    const dim3 blk(256);
    const dim3 gA(Ss / 64, Bb * Hh);
    const int splD = nD / (256 * 8);
    const int splF = nF / (256 * 8);

    const float* cur_x = x;
    for (int l = 0; l < Ll; l++) {
        const float* bo_l = bo + (size_t)l * Dd;
        const float* g1_l = ln1_g + (size_t)l * Dd;
        const float* c1_l = ln1_b + (size_t)l * Dd;
        const float* b1_l = b1 + (size_t)l * Ff;
        const float* b2_l = b2 + (size_t)l * Dd;
        const float* g2_l = ln2_g + (size_t)l * Dd;
        const float* c2_l = ln2_b + (size_t)l * Dd;

        // Fused QKV: N=2304, epilogue routes to q/k/v
        split_act_kernel<<<splD, blk>>>(cur_x, pah, pal, nD);
        tc_gemm_kernel<<<dim3(18, 64), blk, GEMM_SMEM>>>(
            pah, pal, qkvh + l * 3 * DD, qkvl + l * 3 * DD, nullptr,
            pq, pk, pv, 2304, 768, 2);

        // causal flash attention -> merged av in g_attn
        flash_attn_kernel<<<gA, blk, FLASH_SMEM>>>(pq, pk, pv, pattn);

        // attn_out = av @ Wo + bo  (into pq)
        split_act_kernel<<<splD, blk>>>(pattn, pah, pal, nD);
        tc_gemm_kernel<<<dim3(6, 64), blk, GEMM_SMEM>>>(
            pah, pal, woh + l * DD, wol + l * DD, bo_l,
            pq, pq, pq, 768, 768, 0);

        // h = LN(x + attn_out)
        ln_kernel<<<Mrows, blk>>>(cur_x, pq, g1_l, c1_l, px);

        // mid = gelu(h @ W1 + b1)
        split_act_kernel<<<splD, blk>>>(px, pah, pal, nD);
        tc_gemm_kernel<<<dim3(24, 64), blk, GEMM_SMEM>>>(
            pah, pal, w1h + l * DF, w1l + l * DF, b1_l,
            pmid, pmid, pmid, 3072, 768, 1);

        // f = mid @ W2 + b2  (into pattn)
        split_act_kernel<<<splF, blk>>>(pmid, pah, pal, nF);
        tc_gemm_kernel<<<dim3(6, 64), blk, GEMM_SMEM>>>(
            pah, pal, w2h + l * DF, w2l + l * DF, b2_l,
            pattn, pattn, pattn, 768, 3072, 0);

        // x_next = LN(h + f); last layer writes d_out
        float* dst = (l == Ll - 1) ? (float*)d_out : px;
        ln_kernel<<<Mrows, blk>>>(px, pattn, g2_l, c2_l, dst);

        cur_x = px;
    }
}